// round 14
// baseline (speedup 1.0000x reference)
#include <cuda_runtime.h>
#include <cuda_bf16.h>
#include <cstdint>

// ---------------------------------------------------------------------------
// MultiWorldSSM: emb-gather -> router -> 4x (expm + parallel scan + C proj)
//                -> output GEMM [4096,256]x[256,32000]
// Round 14: all per-world chains batched across worlds into single launches
// (blockIdx.z / column-tile -> world). Brent-Kung scan on one [4096,960]
// buffer. C-projection = one K=960 GEMM with router weights folded in.
// Launch count ~170 -> 41. Output GEMM = R9 mma.sync split-bf16 kernel.
// ---------------------------------------------------------------------------

// world geometry (packed)
__constant__ int c_ds  [4]  = {64, 128, 256, 512};
__constant__ int c_moff[4]  = {0, 4096, 20480, 86016};     // matrix-set offsets
__constant__ int c_koff[4]  = {0, 64, 192, 448};           // u column offsets
__constant__ int c_tw  [15] = {0, 1,1, 2,2,2,2, 3,3,3,3,3,3,3,3};   // col tile -> world
__constant__ int c_tn0 [15] = {0, 0,64, 0,64,128,192, 0,64,128,192,256,320,384,448};
#define MAT_SET 348160     // 64^2+128^2+256^2+512^2

struct Ptr4 { const float* p[4]; };

// -------- static scratch (no allocations allowed) --------
__device__ float g_xe  [4 * 1024 * 256];     // embedded tokens
__device__ float g_pre [4 * 1024 * 256];     // weighted-sum accumulator
__device__ float g_u   [4096 * 960];         // scan buffer, all worlds packed
__device__ float g_P   [MAT_SET];            // expm ping (all worlds)
__device__ float g_Q   [MAT_SET];            // expm pong
__device__ float g_pows[10 * MAT_SET];       // P_l = Ad^(2^l), l=0..9, all worlds
__device__ float g_mean[4 * 256];
__device__ float g_w   [4 * 4];

// ---------------------------------------------------------------------------
__global__ void k_embed(const int* __restrict__ x, const float* __restrict__ emb,
                        float* __restrict__ xe) {
    int r = blockIdx.x;          // 0..4095
    int d = threadIdx.x;         // 0..63 (float4 lanes)
    int tok = x[r];
    reinterpret_cast<float4*>(xe)[(size_t)r * 64 + d] =
        reinterpret_cast<const float4*>(emb)[(size_t)tok * 64 + d];
}

__global__ void k_mean(const float* __restrict__ xe, float* __restrict__ mean) {
    __shared__ float part[4][256];
    int b = blockIdx.x, t = threadIdx.x;          // 4 blocks x 1024 threads
    int d = t & 255, pc = t >> 8;
    const float* p = xe + (size_t)b * 262144 + (size_t)pc * 65536 + d;
    float s0 = 0.f, s1 = 0.f, s2 = 0.f, s3 = 0.f;
    #pragma unroll 4
    for (int i = 0; i < 256; i += 4) {
        s0 += p[(size_t)(i + 0) * 256];
        s1 += p[(size_t)(i + 1) * 256];
        s2 += p[(size_t)(i + 2) * 256];
        s3 += p[(size_t)(i + 3) * 256];
    }
    part[pc][d] = (s0 + s1) + (s2 + s3);
    __syncthreads();
    if (pc == 0)
        mean[b * 256 + d] = (part[0][d] + part[1][d] + part[2][d] + part[3][d])
                            * (1.0f / 1024.0f);
}

__global__ void k_router(const float* __restrict__ mean,
                         const float* __restrict__ rw1, const float* __restrict__ rb1,
                         const float* __restrict__ rw2, const float* __restrict__ rb2,
                         float* __restrict__ w) {
    __shared__ float hid[4][64];
    __shared__ float logit[4][4];
    int t = threadIdx.x;              // 256 threads
    int b = t >> 6, j = t & 63;
    float s0 = rb1[j], s1 = 0.f, s2 = 0.f, s3 = 0.f;
    #pragma unroll 4
    for (int d = 0; d < 256; d += 4) {
        s0 = fmaf(mean[b * 256 + d + 0], rw1[(d + 0) * 64 + j], s0);
        s1 = fmaf(mean[b * 256 + d + 1], rw1[(d + 1) * 64 + j], s1);
        s2 = fmaf(mean[b * 256 + d + 2], rw1[(d + 2) * 64 + j], s2);
        s3 = fmaf(mean[b * 256 + d + 3], rw1[(d + 3) * 64 + j], s3);
    }
    hid[b][j] = fmaxf((s0 + s1) + (s2 + s3), 0.f);
    __syncthreads();
    if (t < 16) {
        int bb = t >> 2, i = t & 3;
        float s = rb2[i];
        for (int k = 0; k < 64; k++) s = fmaf(hid[bb][k], rw2[k * 4 + i], s);
        logit[bb][i] = s;
    }
    __syncthreads();
    if (t < 4) {
        int bb = t;
        float mx = -1e30f;
        for (int i = 0; i < 4; i++) mx = fmaxf(mx, logit[bb][i]);
        float e[4], se = 0.f;
        for (int i = 0; i < 4; i++) { e[i] = __expf(logit[bb][i] - mx); se += e[i]; }
        for (int i = 0; i < 4; i++) w[bb * 4 + i] = e[i] / se;
    }
}

// pre[r,d] = xe[r,d] * sum_i w[b,i] * D_i[d]   (initializes the accumulator)
__global__ void k_dterm(const float* __restrict__ xe, const float* __restrict__ w,
                        const float* __restrict__ D0, const float* __restrict__ D1,
                        const float* __restrict__ D2, const float* __restrict__ D3,
                        float* __restrict__ pre) {
    int r = blockIdx.x, d = threadIdx.x;
    int b = r >> 10;
    float wd = w[b * 4 + 0] * D0[d] + w[b * 4 + 1] * D1[d]
             + w[b * 4 + 2] * D2[d] + w[b * 4 + 3] * D3[d];
    size_t idx = (size_t)r * 256 + d;
    pre[idx] = xe[idx] * wd;
}

// identity into all 4 world regions of a packed matrix set
__global__ void k_ident4(float* __restrict__ base) {
    int i = blockIdx.x * 256 + threadIdx.x;
    if (i >= MAT_SET) return;
    int w = (i < 4096) ? 0 : (i < 20480) ? 1 : (i < 86016) ? 2 : 3;
    int local = i - c_moff[w];
    int ds = c_ds[w];
    base[i] = (local / ds == local % ds) ? 1.0f : 0.0f;
}

// ---------------------------------------------------------------------------
// Batched square GEMM over 4 worlds: C_w = alpha * A_w @ B_w (+I).
// A_w = Ap.p[w]; B_w/C_w = region c_moff[w] of Bbase/Cbase. grid (8,8,4).
// ---------------------------------------------------------------------------
__global__ void k_gemm4sq(Ptr4 Ap, const float* __restrict__ Bbase,
                          float* __restrict__ Cbase, float alpha, int addI) {
    int w = blockIdx.z;
    int ds = c_ds[w];
    int nt = ds >> 6;
    if ((int)blockIdx.x >= nt || (int)blockIdx.y >= nt) return;
    const float* A = Ap.p[w];
    const float* B = Bbase + c_moff[w];
    float* C = Cbase + c_moff[w];
    __shared__ float As[16][65];
    __shared__ float Bs[16][64];
    int n0 = blockIdx.x * 64, m0 = blockIdx.y * 64;
    int t = threadIdx.x;
    int tx = t & 15, ty = t >> 4;
    float acc[4][4] = {};
    for (int kt = 0; kt < ds; kt += 16) {
        #pragma unroll
        for (int i = 0; i < 4; i++) {
            int e = t + i * 256;
            int m = e >> 4, k = e & 15;
            As[k][m] = A[(size_t)(m0 + m) * ds + kt + k];
        }
        #pragma unroll
        for (int i = 0; i < 4; i++) {
            int e = t + i * 256;
            int k = e >> 6, n = e & 63;
            Bs[k][n] = B[(size_t)(kt + k) * ds + n0 + n];
        }
        __syncthreads();
        #pragma unroll
        for (int k = 0; k < 16; k++) {
            float a[4], b[4];
            #pragma unroll
            for (int i = 0; i < 4; i++) a[i] = As[k][ty * 4 + i];
            #pragma unroll
            for (int j = 0; j < 4; j++) b[j] = Bs[k][tx * 4 + j];
            #pragma unroll
            for (int i = 0; i < 4; i++)
                #pragma unroll
                for (int j = 0; j < 4; j++)
                    acc[i][j] = fmaf(a[i], b[j], acc[i][j]);
        }
        __syncthreads();
    }
    #pragma unroll
    for (int i = 0; i < 4; i++) {
        int r = m0 + ty * 4 + i;
        #pragma unroll
        for (int j = 0; j < 4; j++) {
            int c = n0 + tx * 4 + j;
            float v = alpha * acc[i][j];
            if (addI && r == c) v += 1.0f;
            C[(size_t)r * ds + c] = v;
        }
    }
}

// ---------------------------------------------------------------------------
// Batched u = xe @ B_w into u[4096, 960] (world column slices). grid (15, 64).
// ---------------------------------------------------------------------------
__global__ void k_ugemm(const float* __restrict__ xe, Ptr4 Bp,
                        float* __restrict__ u) {
    int ct = blockIdx.x;
    int w = c_tw[ct], n0 = c_tn0[ct], ds = c_ds[w], co = c_koff[w];
    const float* B = Bp.p[w];
    __shared__ float As[16][65];
    __shared__ float Bs[16][64];
    int m0 = blockIdx.y * 64;
    int t = threadIdx.x;
    int tx = t & 15, ty = t >> 4;
    float acc[4][4] = {};
    for (int kt = 0; kt < 256; kt += 16) {
        #pragma unroll
        for (int i = 0; i < 4; i++) {
            int e = t + i * 256;
            int m = e >> 4, k = e & 15;
            As[k][m] = xe[(size_t)(m0 + m) * 256 + kt + k];
        }
        #pragma unroll
        for (int i = 0; i < 4; i++) {
            int e = t + i * 256;
            int k = e >> 6, n = e & 63;
            Bs[k][n] = B[(size_t)(kt + k) * ds + n0 + n];
        }
        __syncthreads();
        #pragma unroll
        for (int k = 0; k < 16; k++) {
            float a[4], b[4];
            #pragma unroll
            for (int i = 0; i < 4; i++) a[i] = As[k][ty * 4 + i];
            #pragma unroll
            for (int j = 0; j < 4; j++) b[j] = Bs[k][tx * 4 + j];
            #pragma unroll
            for (int i = 0; i < 4; i++)
                #pragma unroll
                for (int j = 0; j < 4; j++)
                    acc[i][j] = fmaf(a[i], b[j], acc[i][j]);
        }
        __syncthreads();
    }
    #pragma unroll
    for (int i = 0; i < 4; i++) {
        int r = m0 + ty * 4 + i;
        #pragma unroll
        for (int j = 0; j < 4; j++)
            u[(size_t)r * 960 + co + n0 + tx * 4 + j] = acc[i][j];
    }
}

// ---------------------------------------------------------------------------
// Batched Brent-Kung step (in place): for m in [0, 4*cnt):
//   b = m/cnt, j = m%cnt; dst = b*1024 + j*stride + dstoff; src = dst - half
//   u[dst, w-slice] += u[src, w-slice] @ P_w         grid (15, ceil(4cnt/64))
// ---------------------------------------------------------------------------
__global__ void k_scan4(float* __restrict__ u, const float* __restrict__ Plev,
                        int cnt, int stride, int dstoff, int half) {
    int ct = blockIdx.x;
    int w = c_tw[ct], n0 = c_tn0[ct], ds = c_ds[w], co = c_koff[w];
    const float* P = Plev + c_moff[w];
    __shared__ float As[16][65];
    __shared__ float Bs[16][64];
    int m0 = blockIdx.y * 64;
    int M = 4 * cnt;
    int t = threadIdx.x;
    int tx = t & 15, ty = t >> 4;
    float acc[4][4] = {};
    for (int kt = 0; kt < ds; kt += 16) {
        #pragma unroll
        for (int i = 0; i < 4; i++) {
            int e = t + i * 256;
            int m = e >> 4, k = e & 15;
            int gm = m0 + m; if (gm >= M) gm = M - 1;
            int b = gm / cnt, j = gm - b * cnt;
            int srow = b * 1024 + j * stride + dstoff - half;
            As[k][m] = u[(size_t)srow * 960 + co + kt + k];
        }
        #pragma unroll
        for (int i = 0; i < 4; i++) {
            int e = t + i * 256;
            int k = e >> 6, n = e & 63;
            Bs[k][n] = P[(size_t)(kt + k) * ds + n0 + n];
        }
        __syncthreads();
        #pragma unroll
        for (int k = 0; k < 16; k++) {
            float a[4], b[4];
            #pragma unroll
            for (int i = 0; i < 4; i++) a[i] = As[k][ty * 4 + i];
            #pragma unroll
            for (int j = 0; j < 4; j++) b[j] = Bs[k][tx * 4 + j];
            #pragma unroll
            for (int i = 0; i < 4; i++)
                #pragma unroll
                for (int j = 0; j < 4; j++)
                    acc[i][j] = fmaf(a[i], b[j], acc[i][j]);
        }
        __syncthreads();
    }
    #pragma unroll
    for (int i = 0; i < 4; i++) {
        int gm = m0 + ty * 4 + i;
        if (gm >= M) continue;
        int b = gm / cnt, j = gm - b * cnt;
        size_t drow = (size_t)(b * 1024 + j * stride + dstoff);
        #pragma unroll
        for (int jj = 0; jj < 4; jj++)
            u[drow * 960 + co + n0 + tx * 4 + jj] += acc[i][jj];
    }
}

// ---------------------------------------------------------------------------
// C projection, all worlds in one GEMM:
//   pre[r, c] += sum_w wv[b(r), w] * (h_w[r, :] @ C_w[:, c])
// K = 960 (concatenated states), router weight folded into A-tile load.
// grid (4, 64), 256 threads.
// ---------------------------------------------------------------------------
__global__ void k_cproj(const float* __restrict__ u, Ptr4 Cp,
                        const float* __restrict__ wv, float* __restrict__ pre) {
    __shared__ float As[16][65];
    __shared__ float Bs[16][64];
    __shared__ float sw[16];
    int n0 = blockIdx.x * 64, m0 = blockIdx.y * 64;
    int t = threadIdx.x;
    int tx = t & 15, ty = t >> 4;
    if (t < 16) sw[t] = wv[t];
    __syncthreads();
    float acc[4][4] = {};
    for (int ktile = 0; ktile < 60; ktile++) {
        int kg0 = ktile * 16;
        int w = (ktile < 4) ? 0 : (ktile < 12) ? 1 : (ktile < 28) ? 2 : 3;
        int kl0 = kg0 - c_koff[w];
        const float* C = Cp.p[w];
        #pragma unroll
        for (int i = 0; i < 4; i++) {
            int e = t + i * 256;
            int m = e >> 4, k = e & 15;
            int row = m0 + m;
            As[k][m] = u[(size_t)row * 960 + kg0 + k] * sw[(row >> 10) * 4 + w];
        }
        #pragma unroll
        for (int i = 0; i < 4; i++) {
            int e = t + i * 256;
            int k = e >> 6, n = e & 63;
            Bs[k][n] = C[(size_t)(kl0 + k) * 256 + n0 + n];
        }
        __syncthreads();
        #pragma unroll
        for (int k = 0; k < 16; k++) {
            float a[4], b[4];
            #pragma unroll
            for (int i = 0; i < 4; i++) a[i] = As[k][ty * 4 + i];
            #pragma unroll
            for (int j = 0; j < 4; j++) b[j] = Bs[k][tx * 4 + j];
            #pragma unroll
            for (int i = 0; i < 4; i++)
                #pragma unroll
                for (int j = 0; j < 4; j++)
                    acc[i][j] = fmaf(a[i], b[j], acc[i][j]);
        }
        __syncthreads();
    }
    #pragma unroll
    for (int i = 0; i < 4; i++) {
        int r = m0 + ty * 4 + i;
        #pragma unroll
        for (int j = 0; j < 4; j++) {
            size_t idx = (size_t)r * 256 + n0 + tx * 4 + j;
            pre[idx] += acc[i][j];
        }
    }
}

// ---------------------------------------------------------------------------
// Output GEMM on tensor cores: C[M,N] = A[M,K] @ B[K,N] + bias, via bf16
// 3-pass split (AH*BH + AH*BL + AL*BH), fp32 accumulate. (R9 kernel.)
// ---------------------------------------------------------------------------
__device__ __forceinline__ void ldm_x4(uint32_t* r, uint32_t addr) {
    asm volatile("ldmatrix.sync.aligned.m8n8.x4.shared.b16 {%0,%1,%2,%3}, [%4];"
                 : "=r"(r[0]), "=r"(r[1]), "=r"(r[2]), "=r"(r[3]) : "r"(addr));
}
__device__ __forceinline__ void ldm_x2_t(uint32_t* r, uint32_t addr) {
    asm volatile("ldmatrix.sync.aligned.m8n8.x2.trans.shared.b16 {%0,%1}, [%2];"
                 : "=r"(r[0]), "=r"(r[1]) : "r"(addr));
}
__device__ __forceinline__ void mma_bf16(float* d, const uint32_t* a, const uint32_t* b) {
    asm volatile("mma.sync.aligned.m16n8k16.row.col.f32.bf16.bf16.f32 "
                 "{%0,%1,%2,%3}, {%4,%5,%6,%7}, {%8,%9}, {%0,%1,%2,%3};"
                 : "+f"(d[0]), "+f"(d[1]), "+f"(d[2]), "+f"(d[3])
                 : "r"(a[0]), "r"(a[1]), "r"(a[2]), "r"(a[3]),
                   "r"(b[0]), "r"(b[1]));
}

__global__ __launch_bounds__(256)
void k_gemm_out_tc(const float* __restrict__ A, const float* __restrict__ B,
                   float* __restrict__ C, int M, int N, int K,
                   const float* __restrict__ bias) {
    __shared__ __align__(16) __nv_bfloat16 sAH[128][24];   // row stride 48B
    __shared__ __align__(16) __nv_bfloat16 sAL[128][24];
    __shared__ __align__(16) __nv_bfloat16 sBH[16][136];   // row stride 272B
    __shared__ __align__(16) __nv_bfloat16 sBL[16][136];

    int t = threadIdx.x;
    int lane = t & 31, wid = t >> 5;
    int warpM = wid >> 2, warpN = wid & 3;   // 2 x 4 warps
    int m0 = blockIdx.y * 128;
    int n0 = blockIdx.x * 128;

    float acc[4][4][4] = {};   // [mtile][ntile][reg]

    for (int kt = 0; kt < K; kt += 16) {
        // ---- A tile: 128m x 16k fp32 -> split hi/lo bf16 ----
        #pragma unroll
        for (int i = 0; i < 2; i++) {
            int idx4 = t + i * 256;        // 512 float4 slots
            int m = idx4 >> 2, kq = idx4 & 3;
            float4 v = *reinterpret_cast<const float4*>(
                &A[(size_t)(m0 + m) * K + kt + kq * 4]);
            __nv_bfloat16 h0 = __float2bfloat16_rn(v.x);
            __nv_bfloat16 h1 = __float2bfloat16_rn(v.y);
            __nv_bfloat16 h2 = __float2bfloat16_rn(v.z);
            __nv_bfloat16 h3 = __float2bfloat16_rn(v.w);
            __nv_bfloat16 l0 = __float2bfloat16_rn(v.x - __bfloat162float(h0));
            __nv_bfloat16 l1 = __float2bfloat16_rn(v.y - __bfloat162float(h1));
            __nv_bfloat16 l2 = __float2bfloat16_rn(v.z - __bfloat162float(h2));
            __nv_bfloat16 l3 = __float2bfloat16_rn(v.w - __bfloat162float(h3));
            __nv_bfloat162* pH = reinterpret_cast<__nv_bfloat162*>(&sAH[m][kq * 4]);
            __nv_bfloat162* pL = reinterpret_cast<__nv_bfloat162*>(&sAL[m][kq * 4]);
            pH[0] = __nv_bfloat162(h0, h1); pH[1] = __nv_bfloat162(h2, h3);
            pL[0] = __nv_bfloat162(l0, l1); pL[1] = __nv_bfloat162(l2, l3);
        }
        // ---- B tile: 16k x 128n fp32 -> split hi/lo bf16 ----
        #pragma unroll
        for (int i = 0; i < 2; i++) {
            int idx4 = t + i * 256;
            int k = idx4 >> 5, nq = idx4 & 31;
            float4 v = *reinterpret_cast<const float4*>(
                &B[(size_t)(kt + k) * N + n0 + nq * 4]);
            __nv_bfloat16 h0 = __float2bfloat16_rn(v.x);
            __nv_bfloat16 h1 = __float2bfloat16_rn(v.y);
            __nv_bfloat16 h2 = __float2bfloat16_rn(v.z);
            __nv_bfloat16 h3 = __float2bfloat16_rn(v.w);
            __nv_bfloat16 l0 = __float2bfloat16_rn(v.x - __bfloat162float(h0));
            __nv_bfloat16 l1 = __float2bfloat16_rn(v.y - __bfloat162float(h1));
            __nv_bfloat16 l2 = __float2bfloat16_rn(v.z - __bfloat162float(h2));
            __nv_bfloat16 l3 = __float2bfloat16_rn(v.w - __bfloat162float(h3));
            __nv_bfloat162* pH = reinterpret_cast<__nv_bfloat162*>(&sBH[k][nq * 4]);
            __nv_bfloat162* pL = reinterpret_cast<__nv_bfloat162*>(&sBL[k][nq * 4]);
            pH[0] = __nv_bfloat162(h0, h1); pH[1] = __nv_bfloat162(h2, h3);
            pL[0] = __nv_bfloat162(l0, l1); pL[1] = __nv_bfloat162(l2, l3);
        }
        __syncthreads();

        // ---- fragments ----
        uint32_t aH[4][4], aL[4][4], bH[4][2], bL[4][2];
        int arow_off = ((lane >> 3) & 1) * 8 + (lane & 7);
        int ako = (lane >> 4) * 8;
        #pragma unroll
        for (int mt = 0; mt < 4; mt++) {
            int row = warpM * 64 + mt * 16 + arow_off;
            ldm_x4(aH[mt], (uint32_t)__cvta_generic_to_shared(&sAH[row][ako]));
            ldm_x4(aL[mt], (uint32_t)__cvta_generic_to_shared(&sAL[row][ako]));
        }
        int bkrow = lane & 15;
        #pragma unroll
        for (int nt = 0; nt < 4; nt++) {
            int ncol = warpN * 32 + nt * 8;
            ldm_x2_t(bH[nt], (uint32_t)__cvta_generic_to_shared(&sBH[bkrow][ncol]));
            ldm_x2_t(bL[nt], (uint32_t)__cvta_generic_to_shared(&sBL[bkrow][ncol]));
        }
        // ---- 3-pass split MMA ----
        #pragma unroll
        for (int mt = 0; mt < 4; mt++)
            #pragma unroll
            for (int nt = 0; nt < 4; nt++) {
                mma_bf16(acc[mt][nt], aH[mt], bH[nt]);
                mma_bf16(acc[mt][nt], aH[mt], bL[nt]);
                mma_bf16(acc[mt][nt], aL[mt], bH[nt]);
            }
        __syncthreads();
    }

    // ---- epilogue: + bias, store fp32 ----
    int g = lane >> 2, tg = lane & 3;
    #pragma unroll
    for (int nt = 0; nt < 4; nt++) {
        int c = n0 + warpN * 32 + nt * 8 + tg * 2;
        float b0 = bias[c], b1 = bias[c + 1];
        #pragma unroll
        for (int mt = 0; mt < 4; mt++) {
            int r = m0 + warpM * 64 + mt * 16 + g;
            float2 v0 = make_float2(acc[mt][nt][0] + b0, acc[mt][nt][1] + b1);
            float2 v1 = make_float2(acc[mt][nt][2] + b0, acc[mt][nt][3] + b1);
            *reinterpret_cast<float2*>(&C[(size_t)r * N + c]) = v0;
            *reinterpret_cast<float2*>(&C[(size_t)(r + 8) * N + c]) = v1;
        }
    }
}

// ---------------------------------------------------------------------------
extern "C" void kernel_launch(void* const* d_in, const int* in_sizes, int n_in,
                              void* d_out, int out_size) {
    const int*   x    = (const int*)  d_in[0];
    const float* emb  = (const float*)d_in[1];
    const float* Am[4] = {(const float*)d_in[2],  (const float*)d_in[6],
                          (const float*)d_in[10], (const float*)d_in[14]};
    const float* Bm[4] = {(const float*)d_in[3],  (const float*)d_in[7],
                          (const float*)d_in[11], (const float*)d_in[15]};
    const float* Cm[4] = {(const float*)d_in[4],  (const float*)d_in[8],
                          (const float*)d_in[12], (const float*)d_in[16]};
    const float* Dm[4] = {(const float*)d_in[5],  (const float*)d_in[9],
                          (const float*)d_in[13], (const float*)d_in[17]};
    const float* rw1 = (const float*)d_in[18];
    const float* rb1 = (const float*)d_in[19];
    const float* rw2 = (const float*)d_in[20];
    const float* rb2 = (const float*)d_in[21];
    const float* ow  = (const float*)d_in[22];
    const float* ob  = (const float*)d_in[23];
    float* out = (float*)d_out;

    float *xe, *pre, *ub, *Pb, *Qb, *pows, *meanb, *wb;
    cudaGetSymbolAddress((void**)&xe,    g_xe);
    cudaGetSymbolAddress((void**)&pre,   g_pre);
    cudaGetSymbolAddress((void**)&ub,    g_u);
    cudaGetSymbolAddress((void**)&Pb,    g_P);
    cudaGetSymbolAddress((void**)&Qb,    g_Q);
    cudaGetSymbolAddress((void**)&pows,  g_pows);
    cudaGetSymbolAddress((void**)&meanb, g_mean);
    cudaGetSymbolAddress((void**)&wb,    g_w);

    const int MOFF[4] = {0, 4096, 20480, 86016};

    // 1. embedding gather + router + D-term
    k_embed<<<4096, 64>>>(x, emb, xe);
    k_mean<<<4, 1024>>>(xe, meanb);
    k_router<<<1, 256>>>(meanb, rw1, rb1, rw2, rb2, wb);
    k_dterm<<<4096, 256>>>(xe, wb, Dm[0], Dm[1], Dm[2], Dm[3], pre);

    // 2. expm(0.1*A_w) for all worlds, Taylor order 6 (batched ping-pong).
    k_ident4<<<(MAT_SET + 255) / 256, 256>>>(Pb);
    Ptr4 Ain; for (int w = 0; w < 4; w++) Ain.p[w] = Am[w];
    float* cur = Pb; float* oth = Qb;
    for (int k = 6; k >= 2; k--) {
        k_gemm4sq<<<dim3(8, 8, 4), 256>>>(Ain, cur, oth, 0.1f / (float)k, 1);
        float* tmp = cur; cur = oth; oth = tmp;
    }
    k_gemm4sq<<<dim3(8, 8, 4), 256>>>(Ain, cur, pows, 0.1f, 1);   // pows set 0 = Ad

    // 3. powers: pows[l+1] = pows[l]^2  (P_l = Ad^(2^l))
    for (int l = 0; l < 9; l++) {
        Ptr4 Ap;
        for (int w = 0; w < 4; w++) Ap.p[w] = pows + (size_t)l * MAT_SET + MOFF[w];
        k_gemm4sq<<<dim3(8, 8, 4), 256>>>(Ap, pows + (size_t)l * MAT_SET,
                                          pows + (size_t)(l + 1) * MAT_SET, 1.0f, 0);
    }

    // 4. u = xe @ B_w for all worlds  -> u[4096, 960]
    Ptr4 Bp; for (int w = 0; w < 4; w++) Bp.p[w] = Bm[w];
    k_ugemm<<<dim3(15, 64), 256>>>(xe, Bp, ub);

    // 5. Brent-Kung scan, in place, batched across worlds.
    for (int l = 0; l <= 9; l++) {          // upsweep
        int stride = 2 << l, half = 1 << l;
        int cnt = 1024 >> (l + 1);
        int M = 4 * cnt;
        k_scan4<<<dim3(15, (M + 63) / 64), 256>>>(
            ub, pows + (size_t)l * MAT_SET, cnt, stride, stride - 1, half);
    }
    for (int l = 8; l >= 0; l--) {          // downsweep
        int stride = 2 << l, half = 1 << l;
        int cnt = (1024 >> (l + 1)) - 1;
        if (cnt <= 0) continue;
        int M = 4 * cnt;
        k_scan4<<<dim3(15, (M + 63) / 64), 256>>>(
            ub, pows + (size_t)l * MAT_SET, cnt, stride, stride - 1 + half, half);
    }

    // 6. pre += sum_w w[b,w] * (h_w @ C_w)   (single K=960 GEMM)
    Ptr4 Cp; for (int w = 0; w < 4; w++) Cp.p[w] = Cm[w];
    k_cproj<<<dim3(4, 64), 256>>>(ub, Cp, wb, pre);

    // 7. out = pre @ ow + ob   [4096, 32000] — bf16 split-x3 TC GEMM (R9)
    k_gemm_out_tc<<<dim3(32000 / 128, 4096 / 128), 256>>>(pre, ow, out,
                                                          4096, 32000, 256, ob);
    (void)in_sizes; (void)n_in; (void)out_size;
}

// round 15
// speedup vs baseline: 1.4896x; 1.4896x over previous
#include <cuda_runtime.h>
#include <cuda_bf16.h>
#include <cstdint>

// ---------------------------------------------------------------------------
// MultiWorldSSM: emb-gather -> router -> 4x (expm + parallel scan + C proj)
//                -> output GEMM [4096,256]x[256,32000]
// Round 14: all per-world chains batched across worlds into single launches
// (blockIdx.z / column-tile -> world). Brent-Kung scan on one [4096,960]
// buffer. C-projection = one K=960 GEMM with router weights folded in.
// Launch count ~170 -> 41. Output GEMM = R9 mma.sync split-bf16 kernel.
// ---------------------------------------------------------------------------

// world geometry (packed)
__constant__ int c_ds  [4]  = {64, 128, 256, 512};
__constant__ int c_moff[4]  = {0, 4096, 20480, 86016};     // matrix-set offsets
__constant__ int c_koff[4]  = {0, 64, 192, 448};           // u column offsets
__constant__ int c_tw  [15] = {0, 1,1, 2,2,2,2, 3,3,3,3,3,3,3,3};   // col tile -> world
__constant__ int c_tn0 [15] = {0, 0,64, 0,64,128,192, 0,64,128,192,256,320,384,448};
#define MAT_SET 348160     // 64^2+128^2+256^2+512^2

struct Ptr4 { const float* p[4]; };

// -------- static scratch (no allocations allowed) --------
__device__ float g_xe  [4 * 1024 * 256];     // embedded tokens
__device__ float g_pre [4 * 1024 * 256];     // weighted-sum accumulator
__device__ float g_u   [4096 * 960];         // scan buffer, all worlds packed
__device__ float g_P   [MAT_SET];            // expm ping (all worlds)
__device__ float g_Q   [MAT_SET];            // expm pong
__device__ float g_pows[10 * MAT_SET];       // P_l = Ad^(2^l), l=0..9, all worlds
__device__ float g_mean[4 * 256];
__device__ float g_w   [4 * 4];

// ---------------------------------------------------------------------------
__global__ void k_embed(const int* __restrict__ x, const float* __restrict__ emb,
                        float* __restrict__ xe) {
    int r = blockIdx.x;          // 0..4095
    int d = threadIdx.x;         // 0..63 (float4 lanes)
    int tok = x[r];
    reinterpret_cast<float4*>(xe)[(size_t)r * 64 + d] =
        reinterpret_cast<const float4*>(emb)[(size_t)tok * 64 + d];
}

__global__ void k_mean(const float* __restrict__ xe, float* __restrict__ mean) {
    __shared__ float part[4][256];
    int b = blockIdx.x, t = threadIdx.x;          // 4 blocks x 1024 threads
    int d = t & 255, pc = t >> 8;
    const float* p = xe + (size_t)b * 262144 + (size_t)pc * 65536 + d;
    float s0 = 0.f, s1 = 0.f, s2 = 0.f, s3 = 0.f;
    #pragma unroll 4
    for (int i = 0; i < 256; i += 4) {
        s0 += p[(size_t)(i + 0) * 256];
        s1 += p[(size_t)(i + 1) * 256];
        s2 += p[(size_t)(i + 2) * 256];
        s3 += p[(size_t)(i + 3) * 256];
    }
    part[pc][d] = (s0 + s1) + (s2 + s3);
    __syncthreads();
    if (pc == 0)
        mean[b * 256 + d] = (part[0][d] + part[1][d] + part[2][d] + part[3][d])
                            * (1.0f / 1024.0f);
}

__global__ void k_router(const float* __restrict__ mean,
                         const float* __restrict__ rw1, const float* __restrict__ rb1,
                         const float* __restrict__ rw2, const float* __restrict__ rb2,
                         float* __restrict__ w) {
    __shared__ float hid[4][64];
    __shared__ float logit[4][4];
    int t = threadIdx.x;              // 256 threads
    int b = t >> 6, j = t & 63;
    float s0 = rb1[j], s1 = 0.f, s2 = 0.f, s3 = 0.f;
    #pragma unroll 4
    for (int d = 0; d < 256; d += 4) {
        s0 = fmaf(mean[b * 256 + d + 0], rw1[(d + 0) * 64 + j], s0);
        s1 = fmaf(mean[b * 256 + d + 1], rw1[(d + 1) * 64 + j], s1);
        s2 = fmaf(mean[b * 256 + d + 2], rw1[(d + 2) * 64 + j], s2);
        s3 = fmaf(mean[b * 256 + d + 3], rw1[(d + 3) * 64 + j], s3);
    }
    hid[b][j] = fmaxf((s0 + s1) + (s2 + s3), 0.f);
    __syncthreads();
    if (t < 16) {
        int bb = t >> 2, i = t & 3;
        float s = rb2[i];
        for (int k = 0; k < 64; k++) s = fmaf(hid[bb][k], rw2[k * 4 + i], s);
        logit[bb][i] = s;
    }
    __syncthreads();
    if (t < 4) {
        int bb = t;
        float mx = -1e30f;
        for (int i = 0; i < 4; i++) mx = fmaxf(mx, logit[bb][i]);
        float e[4], se = 0.f;
        for (int i = 0; i < 4; i++) { e[i] = __expf(logit[bb][i] - mx); se += e[i]; }
        for (int i = 0; i < 4; i++) w[bb * 4 + i] = e[i] / se;
    }
}

// pre[r,d] = xe[r,d] * sum_i w[b,i] * D_i[d]   (initializes the accumulator)
__global__ void k_dterm(const float* __restrict__ xe, const float* __restrict__ w,
                        const float* __restrict__ D0, const float* __restrict__ D1,
                        const float* __restrict__ D2, const float* __restrict__ D3,
                        float* __restrict__ pre) {
    int r = blockIdx.x, d = threadIdx.x;
    int b = r >> 10;
    float wd = w[b * 4 + 0] * D0[d] + w[b * 4 + 1] * D1[d]
             + w[b * 4 + 2] * D2[d] + w[b * 4 + 3] * D3[d];
    size_t idx = (size_t)r * 256 + d;
    pre[idx] = xe[idx] * wd;
}

// identity into all 4 world regions of a packed matrix set
__global__ void k_ident4(float* __restrict__ base) {
    int i = blockIdx.x * 256 + threadIdx.x;
    if (i >= MAT_SET) return;
    int w = (i < 4096) ? 0 : (i < 20480) ? 1 : (i < 86016) ? 2 : 3;
    int local = i - c_moff[w];
    int ds = c_ds[w];
    base[i] = (local / ds == local % ds) ? 1.0f : 0.0f;
}

// ---------------------------------------------------------------------------
// Batched square GEMM over 4 worlds: C_w = alpha * A_w @ B_w (+I).
// A_w = Ap.p[w]; B_w/C_w = region c_moff[w] of Bbase/Cbase. grid (8,8,4).
// ---------------------------------------------------------------------------
__global__ void k_gemm4sq(Ptr4 Ap, const float* __restrict__ Bbase,
                          float* __restrict__ Cbase, float alpha, int addI) {
    int w = blockIdx.z;
    int ds = c_ds[w];
    int nt = ds >> 6;
    if ((int)blockIdx.x >= nt || (int)blockIdx.y >= nt) return;
    const float* A = Ap.p[w];
    const float* B = Bbase + c_moff[w];
    float* C = Cbase + c_moff[w];
    __shared__ float As[16][65];
    __shared__ float Bs[16][64];
    int n0 = blockIdx.x * 64, m0 = blockIdx.y * 64;
    int t = threadIdx.x;
    int tx = t & 15, ty = t >> 4;
    float acc[4][4] = {};
    for (int kt = 0; kt < ds; kt += 16) {
        #pragma unroll
        for (int i = 0; i < 4; i++) {
            int e = t + i * 256;
            int m = e >> 4, k = e & 15;
            As[k][m] = A[(size_t)(m0 + m) * ds + kt + k];
        }
        #pragma unroll
        for (int i = 0; i < 4; i++) {
            int e = t + i * 256;
            int k = e >> 6, n = e & 63;
            Bs[k][n] = B[(size_t)(kt + k) * ds + n0 + n];
        }
        __syncthreads();
        #pragma unroll
        for (int k = 0; k < 16; k++) {
            float a[4], b[4];
            #pragma unroll
            for (int i = 0; i < 4; i++) a[i] = As[k][ty * 4 + i];
            #pragma unroll
            for (int j = 0; j < 4; j++) b[j] = Bs[k][tx * 4 + j];
            #pragma unroll
            for (int i = 0; i < 4; i++)
                #pragma unroll
                for (int j = 0; j < 4; j++)
                    acc[i][j] = fmaf(a[i], b[j], acc[i][j]);
        }
        __syncthreads();
    }
    #pragma unroll
    for (int i = 0; i < 4; i++) {
        int r = m0 + ty * 4 + i;
        #pragma unroll
        for (int j = 0; j < 4; j++) {
            int c = n0 + tx * 4 + j;
            float v = alpha * acc[i][j];
            if (addI && r == c) v += 1.0f;
            C[(size_t)r * ds + c] = v;
        }
    }
}

// ---------------------------------------------------------------------------
// Batched u = xe @ B_w into u[4096, 960] (world column slices). grid (15, 64).
// ---------------------------------------------------------------------------
__global__ void k_ugemm(const float* __restrict__ xe, Ptr4 Bp,
                        float* __restrict__ u) {
    int ct = blockIdx.x;
    int w = c_tw[ct], n0 = c_tn0[ct], ds = c_ds[w], co = c_koff[w];
    const float* B = Bp.p[w];
    __shared__ float As[16][65];
    __shared__ float Bs[16][64];
    int m0 = blockIdx.y * 64;
    int t = threadIdx.x;
    int tx = t & 15, ty = t >> 4;
    float acc[4][4] = {};
    for (int kt = 0; kt < 256; kt += 16) {
        #pragma unroll
        for (int i = 0; i < 4; i++) {
            int e = t + i * 256;
            int m = e >> 4, k = e & 15;
            As[k][m] = xe[(size_t)(m0 + m) * 256 + kt + k];
        }
        #pragma unroll
        for (int i = 0; i < 4; i++) {
            int e = t + i * 256;
            int k = e >> 6, n = e & 63;
            Bs[k][n] = B[(size_t)(kt + k) * ds + n0 + n];
        }
        __syncthreads();
        #pragma unroll
        for (int k = 0; k < 16; k++) {
            float a[4], b[4];
            #pragma unroll
            for (int i = 0; i < 4; i++) a[i] = As[k][ty * 4 + i];
            #pragma unroll
            for (int j = 0; j < 4; j++) b[j] = Bs[k][tx * 4 + j];
            #pragma unroll
            for (int i = 0; i < 4; i++)
                #pragma unroll
                for (int j = 0; j < 4; j++)
                    acc[i][j] = fmaf(a[i], b[j], acc[i][j]);
        }
        __syncthreads();
    }
    #pragma unroll
    for (int i = 0; i < 4; i++) {
        int r = m0 + ty * 4 + i;
        #pragma unroll
        for (int j = 0; j < 4; j++)
            u[(size_t)r * 960 + co + n0 + tx * 4 + j] = acc[i][j];
    }
}

// ---------------------------------------------------------------------------
// Batched Brent-Kung step (in place): for m in [0, 4*cnt):
//   b = m/cnt, j = m%cnt; dst = b*1024 + j*stride + dstoff; src = dst - half
//   u[dst, w-slice] += u[src, w-slice] @ P_w         grid (15, ceil(4cnt/64))
// ---------------------------------------------------------------------------
__global__ void k_scan4(float* __restrict__ u, const float* __restrict__ Plev,
                        int cnt, int stride, int dstoff, int half) {
    int ct = blockIdx.x;
    int w = c_tw[ct], n0 = c_tn0[ct], ds = c_ds[w], co = c_koff[w];
    const float* P = Plev + c_moff[w];
    __shared__ float As[16][65];
    __shared__ float Bs[16][64];
    int m0 = blockIdx.y * 64;
    int M = 4 * cnt;
    int t = threadIdx.x;
    int tx = t & 15, ty = t >> 4;
    float acc[4][4] = {};
    for (int kt = 0; kt < ds; kt += 16) {
        #pragma unroll
        for (int i = 0; i < 4; i++) {
            int e = t + i * 256;
            int m = e >> 4, k = e & 15;
            int gm = m0 + m; if (gm >= M) gm = M - 1;
            int b = gm / cnt, j = gm - b * cnt;
            int srow = b * 1024 + j * stride + dstoff - half;
            As[k][m] = u[(size_t)srow * 960 + co + kt + k];
        }
        #pragma unroll
        for (int i = 0; i < 4; i++) {
            int e = t + i * 256;
            int k = e >> 6, n = e & 63;
            Bs[k][n] = P[(size_t)(kt + k) * ds + n0 + n];
        }
        __syncthreads();
        #pragma unroll
        for (int k = 0; k < 16; k++) {
            float a[4], b[4];
            #pragma unroll
            for (int i = 0; i < 4; i++) a[i] = As[k][ty * 4 + i];
            #pragma unroll
            for (int j = 0; j < 4; j++) b[j] = Bs[k][tx * 4 + j];
            #pragma unroll
            for (int i = 0; i < 4; i++)
                #pragma unroll
                for (int j = 0; j < 4; j++)
                    acc[i][j] = fmaf(a[i], b[j], acc[i][j]);
        }
        __syncthreads();
    }
    #pragma unroll
    for (int i = 0; i < 4; i++) {
        int gm = m0 + ty * 4 + i;
        if (gm >= M) continue;
        int b = gm / cnt, j = gm - b * cnt;
        size_t drow = (size_t)(b * 1024 + j * stride + dstoff);
        #pragma unroll
        for (int jj = 0; jj < 4; jj++)
            u[drow * 960 + co + n0 + tx * 4 + jj] += acc[i][jj];
    }
}

// ---------------------------------------------------------------------------
// C projection, all worlds in one GEMM:
//   pre[r, c] += sum_w wv[b(r), w] * (h_w[r, :] @ C_w[:, c])
// K = 960 (concatenated states), router weight folded into A-tile load.
// grid (4, 64), 256 threads.
// ---------------------------------------------------------------------------
__global__ void k_cproj(const float* __restrict__ u, Ptr4 Cp,
                        const float* __restrict__ wv, float* __restrict__ pre) {
    __shared__ float As[16][65];
    __shared__ float Bs[16][64];
    __shared__ float sw[16];
    int n0 = blockIdx.x * 64, m0 = blockIdx.y * 64;
    int t = threadIdx.x;
    int tx = t & 15, ty = t >> 4;
    if (t < 16) sw[t] = wv[t];
    __syncthreads();
    float acc[4][4] = {};
    for (int ktile = 0; ktile < 60; ktile++) {
        int kg0 = ktile * 16;
        int w = (ktile < 4) ? 0 : (ktile < 12) ? 1 : (ktile < 28) ? 2 : 3;
        int kl0 = kg0 - c_koff[w];
        const float* C = Cp.p[w];
        #pragma unroll
        for (int i = 0; i < 4; i++) {
            int e = t + i * 256;
            int m = e >> 4, k = e & 15;
            int row = m0 + m;
            As[k][m] = u[(size_t)row * 960 + kg0 + k] * sw[(row >> 10) * 4 + w];
        }
        #pragma unroll
        for (int i = 0; i < 4; i++) {
            int e = t + i * 256;
            int k = e >> 6, n = e & 63;
            Bs[k][n] = C[(size_t)(kl0 + k) * 256 + n0 + n];
        }
        __syncthreads();
        #pragma unroll
        for (int k = 0; k < 16; k++) {
            float a[4], b[4];
            #pragma unroll
            for (int i = 0; i < 4; i++) a[i] = As[k][ty * 4 + i];
            #pragma unroll
            for (int j = 0; j < 4; j++) b[j] = Bs[k][tx * 4 + j];
            #pragma unroll
            for (int i = 0; i < 4; i++)
                #pragma unroll
                for (int j = 0; j < 4; j++)
                    acc[i][j] = fmaf(a[i], b[j], acc[i][j]);
        }
        __syncthreads();
    }
    #pragma unroll
    for (int i = 0; i < 4; i++) {
        int r = m0 + ty * 4 + i;
        #pragma unroll
        for (int j = 0; j < 4; j++) {
            size_t idx = (size_t)r * 256 + n0 + tx * 4 + j;
            pre[idx] += acc[i][j];
        }
    }
}

// ---------------------------------------------------------------------------
// Output GEMM on tensor cores: C[M,N] = A[M,K] @ B[K,N] + bias, via bf16
// 3-pass split (AH*BH + AH*BL + AL*BH), fp32 accumulate. (R9 kernel.)
// ---------------------------------------------------------------------------
__device__ __forceinline__ void ldm_x4(uint32_t* r, uint32_t addr) {
    asm volatile("ldmatrix.sync.aligned.m8n8.x4.shared.b16 {%0,%1,%2,%3}, [%4];"
                 : "=r"(r[0]), "=r"(r[1]), "=r"(r[2]), "=r"(r[3]) : "r"(addr));
}
__device__ __forceinline__ void ldm_x2_t(uint32_t* r, uint32_t addr) {
    asm volatile("ldmatrix.sync.aligned.m8n8.x2.trans.shared.b16 {%0,%1}, [%2];"
                 : "=r"(r[0]), "=r"(r[1]) : "r"(addr));
}
__device__ __forceinline__ void mma_bf16(float* d, const uint32_t* a, const uint32_t* b) {
    asm volatile("mma.sync.aligned.m16n8k16.row.col.f32.bf16.bf16.f32 "
                 "{%0,%1,%2,%3}, {%4,%5,%6,%7}, {%8,%9}, {%0,%1,%2,%3};"
                 : "+f"(d[0]), "+f"(d[1]), "+f"(d[2]), "+f"(d[3])
                 : "r"(a[0]), "r"(a[1]), "r"(a[2]), "r"(a[3]),
                   "r"(b[0]), "r"(b[1]));
}

__global__ __launch_bounds__(256)
void k_gemm_out_tc(const float* __restrict__ A, const float* __restrict__ B,
                   float* __restrict__ C, int M, int N, int K,
                   const float* __restrict__ bias) {
    __shared__ __align__(16) __nv_bfloat16 sAH[128][24];   // row stride 48B
    __shared__ __align__(16) __nv_bfloat16 sAL[128][24];
    __shared__ __align__(16) __nv_bfloat16 sBH[16][136];   // row stride 272B
    __shared__ __align__(16) __nv_bfloat16 sBL[16][136];

    int t = threadIdx.x;
    int lane = t & 31, wid = t >> 5;
    int warpM = wid >> 2, warpN = wid & 3;   // 2 x 4 warps
    int m0 = blockIdx.y * 128;
    int n0 = blockIdx.x * 128;

    float acc[4][4][4] = {};   // [mtile][ntile][reg]

    for (int kt = 0; kt < K; kt += 16) {
        // ---- A tile: 128m x 16k fp32 -> split hi/lo bf16 ----
        #pragma unroll
        for (int i = 0; i < 2; i++) {
            int idx4 = t + i * 256;        // 512 float4 slots
            int m = idx4 >> 2, kq = idx4 & 3;
            float4 v = *reinterpret_cast<const float4*>(
                &A[(size_t)(m0 + m) * K + kt + kq * 4]);
            __nv_bfloat16 h0 = __float2bfloat16_rn(v.x);
            __nv_bfloat16 h1 = __float2bfloat16_rn(v.y);
            __nv_bfloat16 h2 = __float2bfloat16_rn(v.z);
            __nv_bfloat16 h3 = __float2bfloat16_rn(v.w);
            __nv_bfloat16 l0 = __float2bfloat16_rn(v.x - __bfloat162float(h0));
            __nv_bfloat16 l1 = __float2bfloat16_rn(v.y - __bfloat162float(h1));
            __nv_bfloat16 l2 = __float2bfloat16_rn(v.z - __bfloat162float(h2));
            __nv_bfloat16 l3 = __float2bfloat16_rn(v.w - __bfloat162float(h3));
            __nv_bfloat162* pH = reinterpret_cast<__nv_bfloat162*>(&sAH[m][kq * 4]);
            __nv_bfloat162* pL = reinterpret_cast<__nv_bfloat162*>(&sAL[m][kq * 4]);
            pH[0] = __nv_bfloat162(h0, h1); pH[1] = __nv_bfloat162(h2, h3);
            pL[0] = __nv_bfloat162(l0, l1); pL[1] = __nv_bfloat162(l2, l3);
        }
        // ---- B tile: 16k x 128n fp32 -> split hi/lo bf16 ----
        #pragma unroll
        for (int i = 0; i < 2; i++) {
            int idx4 = t + i * 256;
            int k = idx4 >> 5, nq = idx4 & 31;
            float4 v = *reinterpret_cast<const float4*>(
                &B[(size_t)(kt + k) * N + n0 + nq * 4]);
            __nv_bfloat16 h0 = __float2bfloat16_rn(v.x);
            __nv_bfloat16 h1 = __float2bfloat16_rn(v.y);
            __nv_bfloat16 h2 = __float2bfloat16_rn(v.z);
            __nv_bfloat16 h3 = __float2bfloat16_rn(v.w);
            __nv_bfloat16 l0 = __float2bfloat16_rn(v.x - __bfloat162float(h0));
            __nv_bfloat16 l1 = __float2bfloat16_rn(v.y - __bfloat162float(h1));
            __nv_bfloat16 l2 = __float2bfloat16_rn(v.z - __bfloat162float(h2));
            __nv_bfloat16 l3 = __float2bfloat16_rn(v.w - __bfloat162float(h3));
            __nv_bfloat162* pH = reinterpret_cast<__nv_bfloat162*>(&sBH[k][nq * 4]);
            __nv_bfloat162* pL = reinterpret_cast<__nv_bfloat162*>(&sBL[k][nq * 4]);
            pH[0] = __nv_bfloat162(h0, h1); pH[1] = __nv_bfloat162(h2, h3);
            pL[0] = __nv_bfloat162(l0, l1); pL[1] = __nv_bfloat162(l2, l3);
        }
        __syncthreads();

        // ---- fragments ----
        uint32_t aH[4][4], aL[4][4], bH[4][2], bL[4][2];
        int arow_off = ((lane >> 3) & 1) * 8 + (lane & 7);
        int ako = (lane >> 4) * 8;
        #pragma unroll
        for (int mt = 0; mt < 4; mt++) {
            int row = warpM * 64 + mt * 16 + arow_off;
            ldm_x4(aH[mt], (uint32_t)__cvta_generic_to_shared(&sAH[row][ako]));
            ldm_x4(aL[mt], (uint32_t)__cvta_generic_to_shared(&sAL[row][ako]));
        }
        int bkrow = lane & 15;
        #pragma unroll
        for (int nt = 0; nt < 4; nt++) {
            int ncol = warpN * 32 + nt * 8;
            ldm_x2_t(bH[nt], (uint32_t)__cvta_generic_to_shared(&sBH[bkrow][ncol]));
            ldm_x2_t(bL[nt], (uint32_t)__cvta_generic_to_shared(&sBL[bkrow][ncol]));
        }
        // ---- 3-pass split MMA ----
        #pragma unroll
        for (int mt = 0; mt < 4; mt++)
            #pragma unroll
            for (int nt = 0; nt < 4; nt++) {
                mma_bf16(acc[mt][nt], aH[mt], bH[nt]);
                mma_bf16(acc[mt][nt], aH[mt], bL[nt]);
                mma_bf16(acc[mt][nt], aL[mt], bH[nt]);
            }
        __syncthreads();
    }

    // ---- epilogue: + bias, store fp32 ----
    int g = lane >> 2, tg = lane & 3;
    #pragma unroll
    for (int nt = 0; nt < 4; nt++) {
        int c = n0 + warpN * 32 + nt * 8 + tg * 2;
        float b0 = bias[c], b1 = bias[c + 1];
        #pragma unroll
        for (int mt = 0; mt < 4; mt++) {
            int r = m0 + warpM * 64 + mt * 16 + g;
            float2 v0 = make_float2(acc[mt][nt][0] + b0, acc[mt][nt][1] + b1);
            float2 v1 = make_float2(acc[mt][nt][2] + b0, acc[mt][nt][3] + b1);
            *reinterpret_cast<float2*>(&C[(size_t)r * N + c]) = v0;
            *reinterpret_cast<float2*>(&C[(size_t)(r + 8) * N + c]) = v1;
        }
    }
}

// ---------------------------------------------------------------------------
extern "C" void kernel_launch(void* const* d_in, const int* in_sizes, int n_in,
                              void* d_out, int out_size) {
    const int*   x    = (const int*)  d_in[0];
    const float* emb  = (const float*)d_in[1];
    const float* Am[4] = {(const float*)d_in[2],  (const float*)d_in[6],
                          (const float*)d_in[10], (const float*)d_in[14]};
    const float* Bm[4] = {(const float*)d_in[3],  (const float*)d_in[7],
                          (const float*)d_in[11], (const float*)d_in[15]};
    const float* Cm[4] = {(const float*)d_in[4],  (const float*)d_in[8],
                          (const float*)d_in[12], (const float*)d_in[16]};
    const float* Dm[4] = {(const float*)d_in[5],  (const float*)d_in[9],
                          (const float*)d_in[13], (const float*)d_in[17]};
    const float* rw1 = (const float*)d_in[18];
    const float* rb1 = (const float*)d_in[19];
    const float* rw2 = (const float*)d_in[20];
    const float* rb2 = (const float*)d_in[21];
    const float* ow  = (const float*)d_in[22];
    const float* ob  = (const float*)d_in[23];
    float* out = (float*)d_out;

    float *xe, *pre, *ub, *Pb, *Qb, *pows, *meanb, *wb;
    cudaGetSymbolAddress((void**)&xe,    g_xe);
    cudaGetSymbolAddress((void**)&pre,   g_pre);
    cudaGetSymbolAddress((void**)&ub,    g_u);
    cudaGetSymbolAddress((void**)&Pb,    g_P);
    cudaGetSymbolAddress((void**)&Qb,    g_Q);
    cudaGetSymbolAddress((void**)&pows,  g_pows);
    cudaGetSymbolAddress((void**)&meanb, g_mean);
    cudaGetSymbolAddress((void**)&wb,    g_w);

    const int MOFF[4] = {0, 4096, 20480, 86016};

    // 1. embedding gather + router + D-term
    k_embed<<<4096, 64>>>(x, emb, xe);
    k_mean<<<4, 1024>>>(xe, meanb);
    k_router<<<1, 256>>>(meanb, rw1, rb1, rw2, rb2, wb);
    k_dterm<<<4096, 256>>>(xe, wb, Dm[0], Dm[1], Dm[2], Dm[3], pre);

    // 2. expm(0.1*A_w) for all worlds, Taylor order 6 (batched ping-pong).
    k_ident4<<<(MAT_SET + 255) / 256, 256>>>(Pb);
    Ptr4 Ain; for (int w = 0; w < 4; w++) Ain.p[w] = Am[w];
    float* cur = Pb; float* oth = Qb;
    for (int k = 6; k >= 2; k--) {
        k_gemm4sq<<<dim3(8, 8, 4), 256>>>(Ain, cur, oth, 0.1f / (float)k, 1);
        float* tmp = cur; cur = oth; oth = tmp;
    }
    k_gemm4sq<<<dim3(8, 8, 4), 256>>>(Ain, cur, pows, 0.1f, 1);   // pows set 0 = Ad

    // 3. powers: pows[l+1] = pows[l]^2  (P_l = Ad^(2^l))
    for (int l = 0; l < 9; l++) {
        Ptr4 Ap;
        for (int w = 0; w < 4; w++) Ap.p[w] = pows + (size_t)l * MAT_SET + MOFF[w];
        k_gemm4sq<<<dim3(8, 8, 4), 256>>>(Ap, pows + (size_t)l * MAT_SET,
                                          pows + (size_t)(l + 1) * MAT_SET, 1.0f, 0);
    }

    // 4. u = xe @ B_w for all worlds  -> u[4096, 960]
    Ptr4 Bp; for (int w = 0; w < 4; w++) Bp.p[w] = Bm[w];
    k_ugemm<<<dim3(15, 64), 256>>>(xe, Bp, ub);

    // 5. Brent-Kung scan, in place, batched across worlds.
    for (int l = 0; l <= 9; l++) {          // upsweep
        int stride = 2 << l, half = 1 << l;
        int cnt = 1024 >> (l + 1);
        int M = 4 * cnt;
        k_scan4<<<dim3(15, (M + 63) / 64), 256>>>(
            ub, pows + (size_t)l * MAT_SET, cnt, stride, stride - 1, half);
    }
    for (int l = 8; l >= 0; l--) {          // downsweep
        int stride = 2 << l, half = 1 << l;
        int cnt = (1024 >> (l + 1)) - 1;
        if (cnt <= 0) continue;
        int M = 4 * cnt;
        k_scan4<<<dim3(15, (M + 63) / 64), 256>>>(
            ub, pows + (size_t)l * MAT_SET, cnt, stride, stride - 1 + half, half);
    }

    // 6. pre += sum_w w[b,w] * (h_w @ C_w)   (single K=960 GEMM)
    Ptr4 Cp; for (int w = 0; w < 4; w++) Cp.p[w] = Cm[w];
    k_cproj<<<dim3(4, 64), 256>>>(ub, Cp, wb, pre);

    // 7. out = pre @ ow + ob   [4096, 32000] — bf16 split-x3 TC GEMM (R9)
    k_gemm_out_tc<<<dim3(32000 / 128, 4096 / 128), 256>>>(pre, ow, out,
                                                          4096, 32000, 256, ob);
    (void)in_sizes; (void)n_in; (void)out_size;
}